// round 1
// baseline (speedup 1.0000x reference)
#include <cuda_runtime.h>
#include <math.h>

// Problem constants
#define N_ 1024
#define S_ 8
#define I_ 128
#define F_ 1024
#define M_ 512

// Scratch for h[n, s, f]  (32 MB, static device allocation — allowed)
__device__ float g_h[(size_t)N_ * S_ * F_];

__device__ __forceinline__ float sigmoid_f(float x) {
    return 1.0f / (1.0f + expf(-x));
}

// ---------------------------------------------------------------------------
// Kernel A: fused gate GEMMs + LSTM cell epilogue (h0 = c0 = 0, forget gate dead)
//   pre_z[n,f] = sum_i x[n,s,i] * Wz[s,f,i] + bz[s,f]   for z in {i, g, o}
//   h[n,s,f]   = sigmoid(pre_o) * tanh( sigmoid(pre_i) * tanh(pre_g) )
// Block: 256 threads, 64(n) x 64(f) tile, one stream per blockIdx.z.
// ---------------------------------------------------------------------------
__global__ __launch_bounds__(256) void gates_kernel(
    const float* __restrict__ xmod,   // [N, S*I]
    const float* __restrict__ Wxi,    // [S, F, I]
    const float* __restrict__ bi,     // [S, F]
    const float* __restrict__ Wxg,
    const float* __restrict__ bg,
    const float* __restrict__ Wxo,
    const float* __restrict__ bo)
{
    const int s  = blockIdx.z;
    const int n0 = blockIdx.x * 64;
    const int f0 = blockIdx.y * 64;

    __shared__ float xs[32][64];       // [k][n]  (K-transposed)
    __shared__ float ws0[32][64];      // [k][f]  gate i
    __shared__ float ws1[32][64];      // gate g
    __shared__ float ws2[32][64];      // gate o

    const int t  = threadIdx.x;
    const int tx = t & 15;             // f microtile
    const int ty = t >> 4;             // n microtile

    float acc0[4][4] = {};
    float acc1[4][4] = {};
    float acc2[4][4] = {};

    const float* Wi = Wxi + (size_t)s * F_ * I_;
    const float* Wg = Wxg + (size_t)s * F_ * I_;
    const float* Wo = Wxo + (size_t)s * F_ * I_;

    for (int k0 = 0; k0 < I_; k0 += 32) {
        // Load x tile: 64 rows x 32 k = 512 float4, 2 per thread
        #pragma unroll
        for (int r = 0; r < 2; ++r) {
            int idx = t + r * 256;
            int row = idx >> 3;            // 0..63
            int k4  = (idx & 7) * 4;       // 0..28
            float4 v = *reinterpret_cast<const float4*>(
                &xmod[(size_t)(n0 + row) * (S_ * I_) + s * I_ + k0 + k4]);
            xs[k4 + 0][row] = v.x; xs[k4 + 1][row] = v.y;
            xs[k4 + 2][row] = v.z; xs[k4 + 3][row] = v.w;
        }
        // Load 3 gate weight tiles
        #pragma unroll
        for (int r = 0; r < 2; ++r) {
            int idx = t + r * 256;
            int row = idx >> 3;
            int k4  = (idx & 7) * 4;
            size_t goff = (size_t)(f0 + row) * I_ + k0 + k4;
            float4 vi = *reinterpret_cast<const float4*>(&Wi[goff]);
            float4 vg = *reinterpret_cast<const float4*>(&Wg[goff]);
            float4 vo = *reinterpret_cast<const float4*>(&Wo[goff]);
            ws0[k4 + 0][row] = vi.x; ws0[k4 + 1][row] = vi.y;
            ws0[k4 + 2][row] = vi.z; ws0[k4 + 3][row] = vi.w;
            ws1[k4 + 0][row] = vg.x; ws1[k4 + 1][row] = vg.y;
            ws1[k4 + 2][row] = vg.z; ws1[k4 + 3][row] = vg.w;
            ws2[k4 + 0][row] = vo.x; ws2[k4 + 1][row] = vo.y;
            ws2[k4 + 2][row] = vo.z; ws2[k4 + 3][row] = vo.w;
        }
        __syncthreads();

        #pragma unroll
        for (int kk = 0; kk < 32; ++kk) {
            float4 a4 = *reinterpret_cast<const float4*>(&xs[kk][ty * 4]);
            float4 b04 = *reinterpret_cast<const float4*>(&ws0[kk][tx * 4]);
            float4 b14 = *reinterpret_cast<const float4*>(&ws1[kk][tx * 4]);
            float4 b24 = *reinterpret_cast<const float4*>(&ws2[kk][tx * 4]);
            const float a[4]  = {a4.x, a4.y, a4.z, a4.w};
            const float b0[4] = {b04.x, b04.y, b04.z, b04.w};
            const float b1[4] = {b14.x, b14.y, b14.z, b14.w};
            const float b2[4] = {b24.x, b24.y, b24.z, b24.w};
            #pragma unroll
            for (int i2 = 0; i2 < 4; ++i2) {
                #pragma unroll
                for (int j = 0; j < 4; ++j) {
                    acc0[i2][j] = fmaf(a[i2], b0[j], acc0[i2][j]);
                    acc1[i2][j] = fmaf(a[i2], b1[j], acc1[i2][j]);
                    acc2[i2][j] = fmaf(a[i2], b2[j], acc2[i2][j]);
                }
            }
        }
        __syncthreads();
    }

    // Epilogue: bias + activations + cell update, store h
    #pragma unroll
    for (int i2 = 0; i2 < 4; ++i2) {
        const int n = n0 + ty * 4 + i2;
        float4 hv;
        float* hvp = reinterpret_cast<float*>(&hv);
        #pragma unroll
        for (int j = 0; j < 4; ++j) {
            const int f = f0 + tx * 4 + j;
            float gi = sigmoid_f(acc0[i2][j] + bi[s * F_ + f]);
            float gg = tanhf(acc1[i2][j] + bg[s * F_ + f]);
            float go = sigmoid_f(acc2[i2][j] + bo[s * F_ + f]);
            float c  = gi * gg;            // c0 == 0 -> forget gate irrelevant
            hvp[j]   = go * tanhf(c);
        }
        *reinterpret_cast<float4*>(
            &g_h[(size_t)n * (S_ * F_) + s * F_ + f0 + tx * 4]) = hv;
    }
}

// ---------------------------------------------------------------------------
// Kernel B: out[n, s*M + m] = sum_f h[n,s,f] * Wout[s,m,f] + bout[s,m]
// Block: 256 threads, 64(n) x 64(m) tile, one stream per blockIdx.z.
// ---------------------------------------------------------------------------
__global__ __launch_bounds__(256) void out_kernel(
    const float* __restrict__ Wout,   // [S, M, F]
    const float* __restrict__ bout,   // [S, M]
    float* __restrict__ out)          // [N, S*M]
{
    const int s  = blockIdx.z;
    const int n0 = blockIdx.x * 64;
    const int m0 = blockIdx.y * 64;

    __shared__ float hs[32][64];      // [k][n]
    __shared__ float wos[32][64];     // [k][m]

    const int t  = threadIdx.x;
    const int tx = t & 15;
    const int ty = t >> 4;

    float acc[4][4] = {};

    const float* W = Wout + (size_t)s * M_ * F_;

    for (int k0 = 0; k0 < F_; k0 += 32) {
        #pragma unroll
        for (int r = 0; r < 2; ++r) {
            int idx = t + r * 256;
            int row = idx >> 3;
            int k4  = (idx & 7) * 4;
            float4 v = *reinterpret_cast<const float4*>(
                &g_h[(size_t)(n0 + row) * (S_ * F_) + s * F_ + k0 + k4]);
            hs[k4 + 0][row] = v.x; hs[k4 + 1][row] = v.y;
            hs[k4 + 2][row] = v.z; hs[k4 + 3][row] = v.w;

            float4 w = *reinterpret_cast<const float4*>(
                &W[(size_t)(m0 + row) * F_ + k0 + k4]);
            wos[k4 + 0][row] = w.x; wos[k4 + 1][row] = w.y;
            wos[k4 + 2][row] = w.z; wos[k4 + 3][row] = w.w;
        }
        __syncthreads();

        #pragma unroll
        for (int kk = 0; kk < 32; ++kk) {
            float4 a4 = *reinterpret_cast<const float4*>(&hs[kk][ty * 4]);
            float4 b4 = *reinterpret_cast<const float4*>(&wos[kk][tx * 4]);
            const float a[4] = {a4.x, a4.y, a4.z, a4.w};
            const float b[4] = {b4.x, b4.y, b4.z, b4.w};
            #pragma unroll
            for (int i2 = 0; i2 < 4; ++i2) {
                #pragma unroll
                for (int j = 0; j < 4; ++j) {
                    acc[i2][j] = fmaf(a[i2], b[j], acc[i2][j]);
                }
            }
        }
        __syncthreads();
    }

    // Epilogue: + bias, store
    #pragma unroll
    for (int i2 = 0; i2 < 4; ++i2) {
        const int n = n0 + ty * 4 + i2;
        const int m = m0 + tx * 4;
        float4 bv = *reinterpret_cast<const float4*>(&bout[s * M_ + m]);
        float4 ov;
        ov.x = acc[i2][0] + bv.x;
        ov.y = acc[i2][1] + bv.y;
        ov.z = acc[i2][2] + bv.z;
        ov.w = acc[i2][3] + bv.w;
        *reinterpret_cast<float4*>(
            &out[(size_t)n * (S_ * M_) + s * M_ + m]) = ov;
    }
}

// ---------------------------------------------------------------------------
// Launch. Input order (metadata): modulation, Wxi, Whi, bi, Wxf, Whf, bf,
// Wxg, Whg, bg, Wxo, Who, bo, Wout, bout.
// Whi/Whf/Whg/Who unused (h0 == 0). Wxf/bf unused (c0 == 0 kills forget gate).
// ---------------------------------------------------------------------------
extern "C" void kernel_launch(void* const* d_in, const int* in_sizes, int n_in,
                              void* d_out, int out_size)
{
    const float* mod  = (const float*)d_in[0];
    const float* Wxi  = (const float*)d_in[1];
    const float* bi   = (const float*)d_in[3];
    const float* Wxg  = (const float*)d_in[7];
    const float* bg   = (const float*)d_in[9];
    const float* Wxo  = (const float*)d_in[10];
    const float* bo   = (const float*)d_in[12];
    const float* Wout = (const float*)d_in[13];
    const float* bout = (const float*)d_in[14];
    float* out = (float*)d_out;

    dim3 gridA(N_ / 64, F_ / 64, S_);   // 16 x 16 x 8
    dim3 gridB(N_ / 64, M_ / 64, S_);   // 16 x 8 x 8
    gates_kernel<<<gridA, 256>>>(mod, Wxi, bi, Wxg, bg, Wxo, bo);
    out_kernel<<<gridB, 256>>>(Wout, bout, out);
}

// round 3
// speedup vs baseline: 2.8667x; 2.8667x over previous
#include <cuda_runtime.h>
#include <cuda_bf16.h>
#include <stdint.h>

#define N_ 1024
#define S_ 8
#define I_ 128
#define F_ 1024
#define M_ 512

// bf16 hi/lo scratch (converted once per launch)
__device__ __nv_bfloat16 g_xhi[(size_t)N_ * S_ * I_];     // 1M
__device__ __nv_bfloat16 g_xlo[(size_t)N_ * S_ * I_];
__device__ __nv_bfloat16 g_wghi[(size_t)3 * S_ * F_ * I_]; // 3M  (gates i,g,o)
__device__ __nv_bfloat16 g_wglo[(size_t)3 * S_ * F_ * I_];
__device__ __nv_bfloat16 g_wouthi[(size_t)S_ * M_ * F_];   // 4M
__device__ __nv_bfloat16 g_woutlo[(size_t)S_ * M_ * F_];
__device__ __nv_bfloat16 g_hhi[(size_t)N_ * S_ * F_];      // 8M
__device__ __nv_bfloat16 g_hlo[(size_t)N_ * S_ * F_];

// ---------------------------------------------------------------------------
// helpers
// ---------------------------------------------------------------------------
__device__ __forceinline__ uint32_t smem_u32(const void* p) {
    uint32_t a;
    asm("{ .reg .u64 t; cvta.to.shared.u64 t, %1; cvt.u32.u64 %0, t; }"
        : "=r"(a) : "l"(p));
    return a;
}
__device__ __forceinline__ void cp16(uint32_t dst, const void* src) {
    asm volatile("cp.async.cg.shared.global [%0], [%1], 16;" :: "r"(dst), "l"(src));
}
__device__ __forceinline__ void cp_commit() { asm volatile("cp.async.commit_group;"); }
template <int Nw> __device__ __forceinline__ void cp_wait() {
    asm volatile("cp.async.wait_group %0;" :: "n"(Nw));
}
__device__ __forceinline__ void ldsm4(uint32_t* r, uint32_t addr) {
    asm volatile("ldmatrix.sync.aligned.m8n8.x4.shared.b16 {%0,%1,%2,%3}, [%4];"
                 : "=r"(r[0]), "=r"(r[1]), "=r"(r[2]), "=r"(r[3]) : "r"(addr));
}
__device__ __forceinline__ void mma16816(float* c, const uint32_t* a, const uint32_t* b) {
    asm volatile(
        "mma.sync.aligned.m16n8k16.row.col.f32.bf16.bf16.f32 "
        "{%0,%1,%2,%3}, {%4,%5,%6,%7}, {%8,%9}, {%0,%1,%2,%3};"
        : "+f"(c[0]), "+f"(c[1]), "+f"(c[2]), "+f"(c[3])
        : "r"(a[0]), "r"(a[1]), "r"(a[2]), "r"(a[3]), "r"(b[0]), "r"(b[1]));
}
__device__ __forceinline__ float fexp(float x) {
    float y;
    asm("ex2.approx.f32 %0, %1;" : "=f"(y) : "f"(x * 1.4426950408889634f));
    return y;
}
__device__ __forceinline__ float frcp(float x) {
    float y;
    asm("rcp.approx.f32 %0, %1;" : "=f"(y) : "f"(x));
    return y;
}
__device__ __forceinline__ float sigmoid_f(float x) { return frcp(1.0f + fexp(-x)); }
__device__ __forceinline__ float tanh_f(float x)    { return 1.0f - 2.0f * frcp(1.0f + fexp(2.0f * x)); }

__device__ __forceinline__ void split2(float f, __nv_bfloat16& h, __nv_bfloat16& l) {
    h = __float2bfloat16_rn(f);
    l = __float2bfloat16_rn(f - __bfloat162float(h));
}
__device__ __forceinline__ uint32_t pack2(__nv_bfloat16 a, __nv_bfloat16 b) {
    union { __nv_bfloat162 v; uint32_t u; } cv;
    cv.v.x = a; cv.v.y = b;
    return cv.u;
}
__device__ __forceinline__ void split8(const float* f, uint4& H, uint4& L) {
    uint32_t* Hp = (uint32_t*)&H;
    uint32_t* Lp = (uint32_t*)&L;
#pragma unroll
    for (int j = 0; j < 4; ++j) {
        __nv_bfloat16 h0, l0, h1, l1;
        split2(f[j * 2 + 0], h0, l0);
        split2(f[j * 2 + 1], h1, l1);
        Hp[j] = pack2(h0, h1);
        Lp[j] = pack2(l0, l1);
    }
}

// ---------------------------------------------------------------------------
// Kernel 0: fp32 -> bf16 hi/lo split for x, gate weights, Wout
// 8M fp32 total; each thread converts 8.
// ---------------------------------------------------------------------------
__global__ __launch_bounds__(256) void convert_kernel(
    const float* __restrict__ x,
    const float* __restrict__ wi, const float* __restrict__ wg,
    const float* __restrict__ wo, const float* __restrict__ wout)
{
    const int item = blockIdx.x * 256 + threadIdx.x;   // 0 .. 1048575
    const float* src;
    __nv_bfloat16 *dhi, *dlo;
    size_t off;
    if (item < 131072)       { src = x;    off = (size_t)item * 8;              dhi = g_xhi;    dlo = g_xlo; }
    else if (item < 262144)  { src = wi;   off = (size_t)(item - 131072) * 8;   dhi = g_wghi;   dlo = g_wglo; }
    else if (item < 393216)  { src = wg;   off = (size_t)(item - 262144) * 8;   dhi = g_wghi + 1048576; dlo = g_wglo + 1048576; }
    else if (item < 524288)  { src = wo;   off = (size_t)(item - 393216) * 8;   dhi = g_wghi + 2097152; dlo = g_wglo + 2097152; }
    else                     { src = wout; off = (size_t)(item - 524288) * 8;   dhi = g_wouthi; dlo = g_woutlo; }
    float v[8];
    *(float4*)&v[0] = *(const float4*)&src[off + 0];
    *(float4*)&v[4] = *(const float4*)&src[off + 4];
    uint4 H, L;
    split8(v, H, L);
    *(uint4*)&dhi[off] = H;
    *(uint4*)&dlo[off] = L;
}

// ---------------------------------------------------------------------------
// Kernel A: gates. CTA = 128(n) x 64(f), stream s, 3 gates fused.
// bf16x3 split via mma.sync. Epilogue: activations, h -> bf16 hi/lo.
// smem: A_hi/A_lo [128][136], per gate B_hi/B_lo [64][136]  (pad 8 -> stride 272B)
// ---------------------------------------------------------------------------
#define GROWB 272
#define GSA_HI 0
#define GSA_LO 34816
#define GSB    69632
#define GSBSZ  34816      /* per gate: hi 17408 + lo 17408 */
#define GATES_SMEM 174080

__global__ __launch_bounds__(256, 1) void gates_mma(const float* __restrict__ bi,
                                                    const float* __restrict__ bg,
                                                    const float* __restrict__ bo)
{
    extern __shared__ char smem[];
    const uint32_t sb = smem_u32(smem);
    const int t = threadIdx.x;
    const int lane = t & 31, wid = t >> 5;
    const int wm = wid & 3;        // n group (4 x 32)
    const int wn = wid >> 2;       // f group (2 x 32)
    const int n0 = blockIdx.x * 128;
    const int f0 = blockIdx.y * 64;
    const int s  = blockIdx.z;

    // ---- async loads: A (x) 128x128 hi/lo, B (W) 3 x 64x128 hi/lo ----
    {
        const __nv_bfloat16* asrcs[2] = { g_xhi, g_xlo };
#pragma unroll
        for (int m = 0; m < 2; ++m) {
#pragma unroll
            for (int it = 0; it < 8; ++it) {
                int item = t + it * 256;           // 0..2047
                int row = item >> 4, seg = item & 15;
                const __nv_bfloat16* src = asrcs[m] + (size_t)(n0 + row) * (S_ * I_) + s * I_ + seg * 8;
                cp16(sb + (m ? GSA_LO : GSA_HI) + row * GROWB + seg * 16, src);
            }
        }
#pragma unroll
        for (int z = 0; z < 3; ++z) {
            const size_t wb = ((size_t)z * S_ + s) * F_ * I_;
#pragma unroll
            for (int m = 0; m < 2; ++m) {
                const __nv_bfloat16* wsrc = (m ? g_wglo : g_wghi) + wb;
                const uint32_t dbase = sb + GSB + z * GSBSZ + m * 17408;
#pragma unroll
                for (int it = 0; it < 4; ++it) {
                    int item = t + it * 256;       // 0..1023
                    int row = item >> 4, seg = item & 15;
                    cp16(dbase + row * GROWB + seg * 16,
                         wsrc + (size_t)(f0 + row) * I_ + seg * 8);
                }
            }
        }
    }
    cp_commit();
    cp_wait<0>();
    __syncthreads();

    // ---- compute ----
    float C[3][8][4];
#pragma unroll
    for (int z = 0; z < 3; ++z)
#pragma unroll
        for (int i = 0; i < 8; ++i)
#pragma unroll
            for (int j = 0; j < 4; ++j) C[z][i][j] = 0.0f;

    const int a_row  = lane & 15;
    const int a_colb = (lane >> 4) * 16;
    const int b_row  = (lane & 7) + ((lane >> 4) & 1) * 8;
    const int b_colb = ((lane >> 3) & 1) * 16;

#pragma unroll
    for (int ks = 0; ks < 8; ++ks) {
        const int kb = ks * 32;    // byte offset of k0 within row
        uint32_t Ahi[2][4], Alo[2][4];
#pragma unroll
        for (int mt = 0; mt < 2; ++mt) {
            uint32_t ra = (wm * 32 + mt * 16 + a_row) * GROWB + a_colb + kb;
            ldsm4(Ahi[mt], sb + GSA_HI + ra);
            ldsm4(Alo[mt], sb + GSA_LO + ra);
        }
#pragma unroll
        for (int z = 0; z < 3; ++z) {
            uint32_t Bhi[4][2], Blo[4][2];
#pragma unroll
            for (int p = 0; p < 2; ++p) {
                uint32_t rb = (wn * 32 + p * 16 + b_row) * GROWB + b_colb + kb;
                uint32_t r[4];
                ldsm4(r, sb + GSB + z * GSBSZ + rb);
                Bhi[p * 2 + 0][0] = r[0]; Bhi[p * 2 + 0][1] = r[1];
                Bhi[p * 2 + 1][0] = r[2]; Bhi[p * 2 + 1][1] = r[3];
                ldsm4(r, sb + GSB + z * GSBSZ + 17408 + rb);
                Blo[p * 2 + 0][0] = r[0]; Blo[p * 2 + 0][1] = r[1];
                Blo[p * 2 + 1][0] = r[2]; Blo[p * 2 + 1][1] = r[3];
            }
#pragma unroll
            for (int mt = 0; mt < 2; ++mt)
#pragma unroll
                for (int nt = 0; nt < 4; ++nt) {
                    float* c = C[z][mt * 4 + nt];
                    mma16816(c, Ahi[mt], Bhi[nt]);
                    mma16816(c, Ahi[mt], Blo[nt]);
                    mma16816(c, Alo[mt], Bhi[nt]);
                }
        }
    }

    // ---- epilogue ----
#pragma unroll
    for (int mt = 0; mt < 2; ++mt) {
#pragma unroll
        for (int nt = 0; nt < 4; ++nt) {
            const int idx = mt * 4 + nt;
            const int r0 = n0 + wm * 32 + mt * 16 + (lane >> 2);
            const int f  = f0 + wn * 32 + nt * 8 + (lane & 3) * 2;
            float2 vbi = *(const float2*)&bi[s * F_ + f];
            float2 vbg = *(const float2*)&bg[s * F_ + f];
            float2 vbo = *(const float2*)&bo[s * F_ + f];
#pragma unroll
            for (int half = 0; half < 2; ++half) {   // c0/c1 then c2/c3 (row +8)
                const int r = r0 + half * 8;
                float pi0 = C[0][idx][half * 2 + 0] + vbi.x;
                float pi1 = C[0][idx][half * 2 + 1] + vbi.y;
                float pg0 = C[1][idx][half * 2 + 0] + vbg.x;
                float pg1 = C[1][idx][half * 2 + 1] + vbg.y;
                float po0 = C[2][idx][half * 2 + 0] + vbo.x;
                float po1 = C[2][idx][half * 2 + 1] + vbo.y;
                float h0 = sigmoid_f(po0) * tanh_f(sigmoid_f(pi0) * tanh_f(pg0));
                float h1 = sigmoid_f(po1) * tanh_f(sigmoid_f(pi1) * tanh_f(pg1));
                __nv_bfloat16 h0h, h0l, h1h, h1l;
                split2(h0, h0h, h0l);
                split2(h1, h1h, h1l);
                size_t ob = ((size_t)r * S_ + s) * F_ + f;
                *(uint32_t*)&g_hhi[ob] = pack2(h0h, h1h);
                *(uint32_t*)&g_hlo[ob] = pack2(h0l, h1l);
            }
        }
    }
}

// ---------------------------------------------------------------------------
// Kernel B: out projection. CTA = 128(n) x 128(m), K=1024 in 16 chunks of 64,
// cp.async double-buffered. bf16x3 split via mma.sync.
// smem/stage: A_hi/A_lo [128][72], B_hi/B_lo [128][72] (stride 144B)
// ---------------------------------------------------------------------------
#define OROWB 144
#define OMATSZ 18432            /* 128*144 */
#define OSTAGE 73728            /* 4 matrices */
#define OUT_SMEM 147456

__global__ __launch_bounds__(256, 1) void out_mma(const float* __restrict__ bout,
                                                  float* __restrict__ out)
{
    extern __shared__ char smem[];
    const uint32_t sb = smem_u32(smem);
    const int t = threadIdx.x;
    const int lane = t & 31, wid = t >> 5;
    const int wn4 = wid & 3;       // n group (4 x 32)
    const int wm2 = wid >> 2;      // m group (2 x 64)
    const int n0 = blockIdx.x * 128;
    const int m0 = blockIdx.y * 128;
    const int s  = blockIdx.z;

    auto load_chunk = [&](int kc) {
        const uint32_t stg = sb + (kc & 1) * OSTAGE;
        const int k0 = kc * 64;
#pragma unroll
        for (int it = 0; it < 4; ++it) {
            int item = t + it * 256;           // 0..1023
            int row = item >> 3, seg = item & 7;
            size_t asrc = ((size_t)(n0 + row) * S_ + s) * F_ + k0 + seg * 8;
            cp16(stg + 0 * OMATSZ + row * OROWB + seg * 16, g_hhi + asrc);
            cp16(stg + 1 * OMATSZ + row * OROWB + seg * 16, g_hlo + asrc);
            size_t bsrc = ((size_t)s * M_ + m0 + row) * F_ + k0 + seg * 8;
            cp16(stg + 2 * OMATSZ + row * OROWB + seg * 16, g_wouthi + bsrc);
            cp16(stg + 3 * OMATSZ + row * OROWB + seg * 16, g_woutlo + bsrc);
        }
        cp_commit();
    };

    float C[16][4];
#pragma unroll
    for (int i = 0; i < 16; ++i)
#pragma unroll
        for (int j = 0; j < 4; ++j) C[i][j] = 0.0f;

    const int a_row  = lane & 15;
    const int a_colb = (lane >> 4) * 16;
    const int b_row  = (lane & 7) + ((lane >> 4) & 1) * 8;
    const int b_colb = ((lane >> 3) & 1) * 16;

    load_chunk(0);
    for (int kc = 0; kc < 16; ++kc) {
        if (kc < 15) load_chunk(kc + 1);
        if (kc < 15) cp_wait<1>(); else cp_wait<0>();
        __syncthreads();
        const uint32_t stg = sb + (kc & 1) * OSTAGE;
#pragma unroll
        for (int ks = 0; ks < 4; ++ks) {
            const int kb = ks * 32;
            uint32_t Ahi[2][4], Alo[2][4];
#pragma unroll
            for (int mt = 0; mt < 2; ++mt) {
                uint32_t ra = (wn4 * 32 + mt * 16 + a_row) * OROWB + a_colb + kb;
                ldsm4(Ahi[mt], stg + 0 * OMATSZ + ra);
                ldsm4(Alo[mt], stg + 1 * OMATSZ + ra);
            }
            uint32_t Bhi[8][2], Blo[8][2];
#pragma unroll
            for (int p = 0; p < 4; ++p) {
                uint32_t rb = (wm2 * 64 + p * 16 + b_row) * OROWB + b_colb + kb;
                uint32_t r[4];
                ldsm4(r, stg + 2 * OMATSZ + rb);
                Bhi[p * 2 + 0][0] = r[0]; Bhi[p * 2 + 0][1] = r[1];
                Bhi[p * 2 + 1][0] = r[2]; Bhi[p * 2 + 1][1] = r[3];
                ldsm4(r, stg + 3 * OMATSZ + rb);
                Blo[p * 2 + 0][0] = r[0]; Blo[p * 2 + 0][1] = r[1];
                Blo[p * 2 + 1][0] = r[2]; Blo[p * 2 + 1][1] = r[3];
            }
#pragma unroll
            for (int mt = 0; mt < 2; ++mt)
#pragma unroll
                for (int nt = 0; nt < 8; ++nt) {
                    float* c = C[mt * 8 + nt];
                    mma16816(c, Ahi[mt], Bhi[nt]);
                    mma16816(c, Ahi[mt], Blo[nt]);
                    mma16816(c, Alo[mt], Bhi[nt]);
                }
        }
        __syncthreads();
    }

    // ---- epilogue: + bout, fp32 store ----
#pragma unroll
    for (int mt = 0; mt < 2; ++mt) {
#pragma unroll
        for (int nt = 0; nt < 8; ++nt) {
            const int idx = mt * 8 + nt;
            const int r0 = n0 + wn4 * 32 + mt * 16 + (lane >> 2);
            const int m  = m0 + wm2 * 64 + nt * 8 + (lane & 3) * 2;
            float2 vb = *(const float2*)&bout[s * M_ + m];
#pragma unroll
            for (int half = 0; half < 2; ++half) {
                const int r = r0 + half * 8;
                float2 ov;
                ov.x = C[idx][half * 2 + 0] + vb.x;
                ov.y = C[idx][half * 2 + 1] + vb.y;
                *(float2*)&out[(size_t)r * (S_ * M_) + s * M_ + m] = ov;
            }
        }
    }
}

// ---------------------------------------------------------------------------
// Launch. Inputs: modulation, Wxi, Whi, bi, Wxf, Whf, bf, Wxg, Whg, bg,
// Wxo, Who, bo, Wout, bout. Wh* unused (h0=0); Wxf/bf unused (c0=0).
// ---------------------------------------------------------------------------
extern "C" void kernel_launch(void* const* d_in, const int* in_sizes, int n_in,
                              void* d_out, int out_size)
{
    const float* mod  = (const float*)d_in[0];
    const float* Wxi  = (const float*)d_in[1];
    const float* bi   = (const float*)d_in[3];
    const float* Wxg  = (const float*)d_in[7];
    const float* bg   = (const float*)d_in[9];
    const float* Wxo  = (const float*)d_in[10];
    const float* bo   = (const float*)d_in[12];
    const float* Wout = (const float*)d_in[13];
    const float* bout = (const float*)d_in[14];
    float* out = (float*)d_out;

    cudaFuncSetAttribute(gates_mma, cudaFuncAttributeMaxDynamicSharedMemorySize, GATES_SMEM);
    cudaFuncSetAttribute(out_mma,   cudaFuncAttributeMaxDynamicSharedMemorySize, OUT_SMEM);

    convert_kernel<<<4096, 256>>>(mod, Wxi, Wxg, Wxo, Wout);
    gates_mma<<<dim3(8, 16, 8), 256, GATES_SMEM>>>(bi, bg, bo);
    out_mma<<<dim3(8, 4, 8), 256, OUT_SMEM>>>(bout, out);
}

// round 5
// speedup vs baseline: 5.1953x; 1.8123x over previous
#include <cuda_runtime.h>
#include <cuda_fp16.h>
#include <stdint.h>

#define N_ 1024
#define S_ 8
#define I_ 128
#define F_ 1024
#define M_ 512

// fp16 scratch (converted once per launch)
__device__ __half g_xh[(size_t)N_ * S_ * I_];        // 1M  (x, single fp16)
__device__ __half g_wgh[(size_t)3 * S_ * F_ * I_];   // 3M  (gate weights i,g,o, single fp16)
__device__ __half g_wouthi[(size_t)S_ * M_ * F_];    // 4M  (Wout hi)
__device__ __half g_woutlo[(size_t)S_ * M_ * F_];    // 4M  (Wout lo)
__device__ __half g_h[(size_t)N_ * S_ * F_];         // 8M  (hidden, single fp16)

// ---------------------------------------------------------------------------
// helpers
// ---------------------------------------------------------------------------
__device__ __forceinline__ uint32_t smem_u32(const void* p) {
    uint32_t a;
    asm("{ .reg .u64 t; cvta.to.shared.u64 t, %1; cvt.u32.u64 %0, t; }"
        : "=r"(a) : "l"(p));
    return a;
}
__device__ __forceinline__ void cp16(uint32_t dst, const void* src) {
    asm volatile("cp.async.cg.shared.global [%0], [%1], 16;" :: "r"(dst), "l"(src));
}
__device__ __forceinline__ void cp_commit() { asm volatile("cp.async.commit_group;"); }
template <int Nw> __device__ __forceinline__ void cp_wait() {
    asm volatile("cp.async.wait_group %0;" :: "n"(Nw));
}
__device__ __forceinline__ void ldsm4(uint32_t* r, uint32_t addr) {
    asm volatile("ldmatrix.sync.aligned.m8n8.x4.shared.b16 {%0,%1,%2,%3}, [%4];"
                 : "=r"(r[0]), "=r"(r[1]), "=r"(r[2]), "=r"(r[3]) : "r"(addr));
}
__device__ __forceinline__ void mma16816(float* c, const uint32_t* a, const uint32_t* b) {
    asm volatile(
        "mma.sync.aligned.m16n8k16.row.col.f32.f16.f16.f32 "
        "{%0,%1,%2,%3}, {%4,%5,%6,%7}, {%8,%9}, {%0,%1,%2,%3};"
        : "+f"(c[0]), "+f"(c[1]), "+f"(c[2]), "+f"(c[3])
        : "r"(a[0]), "r"(a[1]), "r"(a[2]), "r"(a[3]), "r"(b[0]), "r"(b[1]));
}
__device__ __forceinline__ float fexp(float x) {
    float y;
    asm("ex2.approx.f32 %0, %1;" : "=f"(y) : "f"(x * 1.4426950408889634f));
    return y;
}
__device__ __forceinline__ float frcp(float x) {
    float y;
    asm("rcp.approx.f32 %0, %1;" : "=f"(y) : "f"(x));
    return y;
}
__device__ __forceinline__ float sigmoid_f(float x) { return frcp(1.0f + fexp(-x)); }
__device__ __forceinline__ float tanh_f(float x)    { return 1.0f - 2.0f * frcp(1.0f + fexp(2.0f * x)); }

__device__ __forceinline__ uint32_t pack2h(__half a, __half b) {
    union { __half2 v; uint32_t u; } cv;
    cv.v = __halves2half2(a, b);
    return cv.u;
}
// 8 fp32 -> 8 fp16 (packed uint4)
__device__ __forceinline__ uint4 cvt8h(const float* f) {
    uint4 H;
    uint32_t* Hp = (uint32_t*)&H;
#pragma unroll
    for (int j = 0; j < 4; ++j)
        Hp[j] = pack2h(__float2half_rn(f[j * 2]), __float2half_rn(f[j * 2 + 1]));
    return H;
}
// 8 fp32 -> hi/lo fp16 split
__device__ __forceinline__ void split8h(const float* f, uint4& H, uint4& L) {
    uint32_t* Hp = (uint32_t*)&H;
    uint32_t* Lp = (uint32_t*)&L;
#pragma unroll
    for (int j = 0; j < 4; ++j) {
        __half h0 = __float2half_rn(f[j * 2]);
        __half h1 = __float2half_rn(f[j * 2 + 1]);
        __half l0 = __float2half_rn(f[j * 2]     - __half2float(h0));
        __half l1 = __float2half_rn(f[j * 2 + 1] - __half2float(h1));
        Hp[j] = pack2h(h0, h1);
        Lp[j] = pack2h(l0, l1);
    }
}

// ---------------------------------------------------------------------------
// Kernel 0: convert. x, gate weights -> fp16; Wout -> fp16 hi/lo.
// 1048576 items x 8 floats.
// ---------------------------------------------------------------------------
__global__ __launch_bounds__(256) void convert_kernel(
    const float* __restrict__ x,
    const float* __restrict__ wi, const float* __restrict__ wg,
    const float* __restrict__ wo, const float* __restrict__ wout)
{
    const int item = blockIdx.x * 256 + threadIdx.x;
    if (item < 524288) {
        const float* src;
        __half* dst;
        size_t off;
        if (item < 131072)      { src = x;  dst = g_xh;            off = (size_t)item * 8; }
        else if (item < 262144) { src = wi; dst = g_wgh;           off = (size_t)(item - 131072) * 8; }
        else if (item < 393216) { src = wg; dst = g_wgh + 1048576; off = (size_t)(item - 262144) * 8; }
        else                    { src = wo; dst = g_wgh + 2097152; off = (size_t)(item - 393216) * 8; }
        float v[8];
        *(float4*)&v[0] = *(const float4*)&src[off + 0];
        *(float4*)&v[4] = *(const float4*)&src[off + 4];
        *(uint4*)&dst[off] = cvt8h(v);
    } else {
        size_t off = (size_t)(item - 524288) * 8;
        float v[8];
        *(float4*)&v[0] = *(const float4*)&wout[off + 0];
        *(float4*)&v[4] = *(const float4*)&wout[off + 4];
        uint4 H, L;
        split8h(v, H, L);
        *(uint4*)&g_wouthi[off] = H;
        *(uint4*)&g_woutlo[off] = L;
    }
}

// ---------------------------------------------------------------------------
// Kernel A: gates. CTA = 128(n) x 64(f), stream s, 3 gates fused, single-pass
// fp16 mma. smem: A [128][136h], 3x B [64][136h] (row stride 272B). 87040 B.
// Epilogue: activations, h -> fp16.
// ---------------------------------------------------------------------------
#define GROWB 272
#define GSB   34816
#define GSBSZ 17408
#define GATES_SMEM 87040

__global__ __launch_bounds__(256, 2) void gates_mma(const float* __restrict__ bi,
                                                    const float* __restrict__ bg,
                                                    const float* __restrict__ bo)
{
    extern __shared__ char smem[];
    const uint32_t sb = smem_u32(smem);
    const int t = threadIdx.x;
    const int lane = t & 31, wid = t >> 5;
    const int wm = wid & 3;        // n group (4 x 32 rows)
    const int wn = wid >> 2;       // f group (2 x 32 cols)
    const int n0 = blockIdx.x * 128;
    const int f0 = blockIdx.y * 64;
    const int s  = blockIdx.z;

    // ---- async loads: A (x) 128x128 fp16, B (W) 3 x 64x128 fp16 ----
#pragma unroll
    for (int it = 0; it < 8; ++it) {
        int item = t + it * 256;               // 0..2047
        int row = item >> 4, seg = item & 15;
        cp16(sb + row * GROWB + seg * 16,
             g_xh + (size_t)(n0 + row) * (S_ * I_) + s * I_ + seg * 8);
    }
#pragma unroll
    for (int z = 0; z < 3; ++z) {
        const __half* wsrc = g_wgh + ((size_t)z * S_ + s) * F_ * I_;
#pragma unroll
        for (int it = 0; it < 4; ++it) {
            int item = t + it * 256;           // 0..1023: 64 rows x 16 segs (FIXED)
            int row = item >> 4, seg = item & 15;
            cp16(sb + GSB + z * GSBSZ + row * GROWB + seg * 16,
                 wsrc + (size_t)(f0 + row) * I_ + seg * 8);
        }
    }
    cp_commit();
    cp_wait<0>();
    __syncthreads();

    // ---- compute: 8 k-steps, 3 gates, 2x4 microtiles, 1 mma each ----
    float C[3][8][4];
#pragma unroll
    for (int z = 0; z < 3; ++z)
#pragma unroll
        for (int i = 0; i < 8; ++i)
#pragma unroll
            for (int j = 0; j < 4; ++j) C[z][i][j] = 0.0f;

    const int a_row  = lane & 15;
    const int a_colb = (lane >> 4) * 16;
    const int b_row  = (lane & 7) + ((lane >> 4) & 1) * 8;
    const int b_colb = ((lane >> 3) & 1) * 16;

#pragma unroll
    for (int ks = 0; ks < 8; ++ks) {
        const int kb = ks * 32;
        uint32_t A[2][4];
#pragma unroll
        for (int mt = 0; mt < 2; ++mt)
            ldsm4(A[mt], sb + (wm * 32 + mt * 16 + a_row) * GROWB + a_colb + kb);
#pragma unroll
        for (int z = 0; z < 3; ++z) {
            uint32_t B[4][2];
#pragma unroll
            for (int p = 0; p < 2; ++p) {
                uint32_t r[4];
                ldsm4(r, sb + GSB + z * GSBSZ
                         + (wn * 32 + p * 16 + b_row) * GROWB + b_colb + kb);
                B[p * 2 + 0][0] = r[0]; B[p * 2 + 0][1] = r[1];
                B[p * 2 + 1][0] = r[2]; B[p * 2 + 1][1] = r[3];
            }
#pragma unroll
            for (int mt = 0; mt < 2; ++mt)
#pragma unroll
                for (int nt = 0; nt < 4; ++nt)
                    mma16816(C[z][mt * 4 + nt], A[mt], B[nt]);
        }
    }

    // ---- epilogue: bias + activations, h -> fp16 ----
#pragma unroll
    for (int mt = 0; mt < 2; ++mt) {
#pragma unroll
        for (int nt = 0; nt < 4; ++nt) {
            const int idx = mt * 4 + nt;
            const int r0 = n0 + wm * 32 + mt * 16 + (lane >> 2);
            const int f  = f0 + wn * 32 + nt * 8 + (lane & 3) * 2;
            float2 vbi = *(const float2*)&bi[s * F_ + f];
            float2 vbg = *(const float2*)&bg[s * F_ + f];
            float2 vbo = *(const float2*)&bo[s * F_ + f];
#pragma unroll
            for (int half = 0; half < 2; ++half) {
                const int r = r0 + half * 8;
                float pi0 = C[0][idx][half * 2 + 0] + vbi.x;
                float pi1 = C[0][idx][half * 2 + 1] + vbi.y;
                float pg0 = C[1][idx][half * 2 + 0] + vbg.x;
                float pg1 = C[1][idx][half * 2 + 1] + vbg.y;
                float po0 = C[2][idx][half * 2 + 0] + vbo.x;
                float po1 = C[2][idx][half * 2 + 1] + vbo.y;
                float h0 = sigmoid_f(po0) * tanh_f(sigmoid_f(pi0) * tanh_f(pg0));
                float h1 = sigmoid_f(po1) * tanh_f(sigmoid_f(pi1) * tanh_f(pg1));
                size_t ob = ((size_t)r * S_ + s) * F_ + f;
                *(uint32_t*)&g_h[ob] = pack2h(__float2half_rn(h0), __float2half_rn(h1));
            }
        }
    }
}

// ---------------------------------------------------------------------------
// Kernel B: out projection. CTA = 128(n) x 128(m), K=1024 in 16 chunks of 64,
// double-buffered. A = h (fp16), B = Wout hi/lo: 2 mma passes.
// smem/stage: A [128][72h], Bhi [128][72h], Blo [128][72h]. 55296 B/stage x2.
// ---------------------------------------------------------------------------
#define OROWB 144
#define OMATSZ 18432
#define OSTAGE 55296
#define OUT_SMEM 110592

__global__ __launch_bounds__(256, 2) void out_mma(const float* __restrict__ bout,
                                                  float* __restrict__ out)
{
    extern __shared__ char smem[];
    const uint32_t sb = smem_u32(smem);
    const int t = threadIdx.x;
    const int lane = t & 31, wid = t >> 5;
    const int wn4 = wid & 3;       // n group (4 x 32 rows)
    const int wm2 = wid >> 2;      // m group (2 x 64 cols)
    const int n0 = blockIdx.x * 128;
    const int m0 = blockIdx.y * 128;
    const int s  = blockIdx.z;

    auto load_chunk = [&](int kc) {
        const uint32_t stg = sb + (kc & 1) * OSTAGE;
        const int k0 = kc * 64;
#pragma unroll
        for (int it = 0; it < 4; ++it) {
            int item = t + it * 256;           // 0..1023: 128 rows x 8 segs (K=64)
            int row = item >> 3, seg = item & 7;
            size_t asrc = ((size_t)(n0 + row) * S_ + s) * F_ + k0 + seg * 8;
            cp16(stg + 0 * OMATSZ + row * OROWB + seg * 16, g_h + asrc);
            size_t bsrc = ((size_t)s * M_ + m0 + row) * F_ + k0 + seg * 8;
            cp16(stg + 1 * OMATSZ + row * OROWB + seg * 16, g_wouthi + bsrc);
            cp16(stg + 2 * OMATSZ + row * OROWB + seg * 16, g_woutlo + bsrc);
        }
        cp_commit();
    };

    float C[16][4];
#pragma unroll
    for (int i = 0; i < 16; ++i)
#pragma unroll
        for (int j = 0; j < 4; ++j) C[i][j] = 0.0f;

    const int a_row  = lane & 15;
    const int a_colb = (lane >> 4) * 16;
    const int b_row  = (lane & 7) + ((lane >> 4) & 1) * 8;
    const int b_colb = ((lane >> 3) & 1) * 16;

    load_chunk(0);
    for (int kc = 0; kc < 16; ++kc) {
        if (kc < 15) load_chunk(kc + 1);
        if (kc < 15) cp_wait<1>(); else cp_wait<0>();
        __syncthreads();
        const uint32_t stg = sb + (kc & 1) * OSTAGE;
#pragma unroll
        for (int ks = 0; ks < 4; ++ks) {
            const int kb = ks * 32;
            uint32_t A[2][4];
#pragma unroll
            for (int mt = 0; mt < 2; ++mt)
                ldsm4(A[mt], stg + (wn4 * 32 + mt * 16 + a_row) * OROWB + a_colb + kb);
            uint32_t Bh[8][2], Bl[8][2];
#pragma unroll
            for (int p = 0; p < 4; ++p) {
                uint32_t rb = (wm2 * 64 + p * 16 + b_row) * OROWB + b_colb + kb;
                uint32_t r[4];
                ldsm4(r, stg + 1 * OMATSZ + rb);
                Bh[p * 2 + 0][0] = r[0]; Bh[p * 2 + 0][1] = r[1];
                Bh[p * 2 + 1][0] = r[2]; Bh[p * 2 + 1][1] = r[3];
                ldsm4(r, stg + 2 * OMATSZ + rb);
                Bl[p * 2 + 0][0] = r[0]; Bl[p * 2 + 0][1] = r[1];
                Bl[p * 2 + 1][0] = r[2]; Bl[p * 2 + 1][1] = r[3];
            }
#pragma unroll
            for (int mt = 0; mt < 2; ++mt)
#pragma unroll
                for (int nt = 0; nt < 8; ++nt) {
                    float* c = C[mt * 8 + nt];
                    mma16816(c, A[mt], Bh[nt]);
                    mma16816(c, A[mt], Bl[nt]);
                }
        }
        __syncthreads();
    }

    // ---- epilogue: + bout, fp32 store ----
#pragma unroll
    for (int mt = 0; mt < 2; ++mt) {
#pragma unroll
        for (int nt = 0; nt < 8; ++nt) {
            const int idx = mt * 8 + nt;
            const int r0 = n0 + wn4 * 32 + mt * 16 + (lane >> 2);
            const int m  = m0 + wm2 * 64 + nt * 8 + (lane & 3) * 2;
            float2 vb = *(const float2*)&bout[s * M_ + m];
#pragma unroll
            for (int half = 0; half < 2; ++half) {
                const int r = r0 + half * 8;
                float2 ov;
                ov.x = C[idx][half * 2 + 0] + vb.x;
                ov.y = C[idx][half * 2 + 1] + vb.y;
                *(float2*)&out[(size_t)r * (S_ * M_) + s * M_ + m] = ov;
            }
        }
    }
}

// ---------------------------------------------------------------------------
// Launch. Inputs: modulation, Wxi, Whi, bi, Wxf, Whf, bf, Wxg, Whg, bg,
// Wxo, Who, bo, Wout, bout. Wh* unused (h0=0); Wxf/bf unused (c0=0).
// ---------------------------------------------------------------------------
extern "C" void kernel_launch(void* const* d_in, const int* in_sizes, int n_in,
                              void* d_out, int out_size)
{
    const float* mod  = (const float*)d_in[0];
    const float* Wxi  = (const float*)d_in[1];
    const float* bi   = (const float*)d_in[3];
    const float* Wxg  = (const float*)d_in[7];
    const float* bg   = (const float*)d_in[9];
    const float* Wxo  = (const float*)d_in[10];
    const float* bo   = (const float*)d_in[12];
    const float* Wout = (const float*)d_in[13];
    const float* bout = (const float*)d_in[14];
    float* out = (float*)d_out;

    cudaFuncSetAttribute(gates_mma, cudaFuncAttributeMaxDynamicSharedMemorySize, GATES_SMEM);
    cudaFuncSetAttribute(out_mma,   cudaFuncAttributeMaxDynamicSharedMemorySize, OUT_SMEM);

    convert_kernel<<<4096, 256>>>(mod, Wxi, Wxg, Wxo, Wout);
    gates_mma<<<dim3(8, 16, 8), 256, GATES_SMEM>>>(bi, bg, bo);
    out_mma<<<dim3(8, 4, 8), 256, OUT_SMEM>>>(bout, out);
}

// round 6
// speedup vs baseline: 6.9348x; 1.3348x over previous
#include <cuda_runtime.h>
#include <cuda_fp16.h>
#include <stdint.h>

#define N_ 1024
#define S_ 8
#define I_ 128
#define F_ 1024
#define M_ 512

// fp16 scratch (converted once per launch)
__device__ __half g_xh[(size_t)N_ * S_ * I_];        // 1M  (x)
__device__ __half g_wgh[(size_t)3 * S_ * F_ * I_];   // 3M  (gate weights i,g,o)
__device__ __half g_wouth[(size_t)S_ * M_ * F_];     // 4M  (Wout)
__device__ __half g_h[(size_t)N_ * S_ * F_];         // 8M  (hidden)

// ---------------------------------------------------------------------------
// helpers
// ---------------------------------------------------------------------------
__device__ __forceinline__ uint32_t smem_u32(const void* p) {
    uint32_t a;
    asm("{ .reg .u64 t; cvta.to.shared.u64 t, %1; cvt.u32.u64 %0, t; }"
        : "=r"(a) : "l"(p));
    return a;
}
__device__ __forceinline__ void cp16(uint32_t dst, const void* src) {
    asm volatile("cp.async.cg.shared.global [%0], [%1], 16;" :: "r"(dst), "l"(src));
}
__device__ __forceinline__ void cp_commit() { asm volatile("cp.async.commit_group;"); }
template <int Nw> __device__ __forceinline__ void cp_wait() {
    asm volatile("cp.async.wait_group %0;" :: "n"(Nw));
}
__device__ __forceinline__ void ldsm4(uint32_t* r, uint32_t addr) {
    asm volatile("ldmatrix.sync.aligned.m8n8.x4.shared.b16 {%0,%1,%2,%3}, [%4];"
                 : "=r"(r[0]), "=r"(r[1]), "=r"(r[2]), "=r"(r[3]) : "r"(addr));
}
__device__ __forceinline__ void mma16816(float* c, const uint32_t* a, const uint32_t* b) {
    asm volatile(
        "mma.sync.aligned.m16n8k16.row.col.f32.f16.f16.f32 "
        "{%0,%1,%2,%3}, {%4,%5,%6,%7}, {%8,%9}, {%0,%1,%2,%3};"
        : "+f"(c[0]), "+f"(c[1]), "+f"(c[2]), "+f"(c[3])
        : "r"(a[0]), "r"(a[1]), "r"(a[2]), "r"(a[3]), "r"(b[0]), "r"(b[1]));
}
__device__ __forceinline__ float fexp(float x) {
    float y;
    asm("ex2.approx.f32 %0, %1;" : "=f"(y) : "f"(x * 1.4426950408889634f));
    return y;
}
__device__ __forceinline__ float frcp(float x) {
    float y;
    asm("rcp.approx.f32 %0, %1;" : "=f"(y) : "f"(x));
    return y;
}
__device__ __forceinline__ float sigmoid_f(float x) { return frcp(1.0f + fexp(-x)); }
__device__ __forceinline__ float tanh_f(float x)    { return 1.0f - 2.0f * frcp(1.0f + fexp(2.0f * x)); }

__device__ __forceinline__ uint32_t pack2h(__half a, __half b) {
    union { __half2 v; uint32_t u; } cv;
    cv.v = __halves2half2(a, b);
    return cv.u;
}
__device__ __forceinline__ uint4 cvt8h(const float* f) {
    uint4 H;
    uint32_t* Hp = (uint32_t*)&H;
#pragma unroll
    for (int j = 0; j < 4; ++j)
        Hp[j] = pack2h(__float2half_rn(f[j * 2]), __float2half_rn(f[j * 2 + 1]));
    return H;
}

// ---------------------------------------------------------------------------
// Kernel 0: convert everything to plain fp16. 1048576 items x 8 floats.
// ---------------------------------------------------------------------------
__global__ __launch_bounds__(256) void convert_kernel(
    const float* __restrict__ x,
    const float* __restrict__ wi, const float* __restrict__ wg,
    const float* __restrict__ wo, const float* __restrict__ wout)
{
    const int item = blockIdx.x * 256 + threadIdx.x;
    const float* src;
    __half* dst;
    size_t off;
    if (item < 131072)      { src = x;    dst = g_xh;            off = (size_t)item * 8; }
    else if (item < 262144) { src = wi;   dst = g_wgh;           off = (size_t)(item - 131072) * 8; }
    else if (item < 393216) { src = wg;   dst = g_wgh + 1048576; off = (size_t)(item - 262144) * 8; }
    else if (item < 524288) { src = wo;   dst = g_wgh + 2097152; off = (size_t)(item - 393216) * 8; }
    else                    { src = wout; dst = g_wouth;         off = (size_t)(item - 524288) * 8; }
    float v[8];
    *(float4*)&v[0] = *(const float4*)&src[off + 0];
    *(float4*)&v[4] = *(const float4*)&src[off + 4];
    *(uint4*)&dst[off] = cvt8h(v);
}

// ---------------------------------------------------------------------------
// Kernel A: gates. CTA = 128(n) x 64(f), stream s, 3 gates fused, single-pass
// fp16 mma. smem: A [128][136h], 3x B [64][136h] (row stride 272B). 87040 B.
// ---------------------------------------------------------------------------
#define GROWB 272
#define GSB   34816
#define GSBSZ 17408
#define GATES_SMEM 87040

__global__ __launch_bounds__(256, 2) void gates_mma(const float* __restrict__ bi,
                                                    const float* __restrict__ bg,
                                                    const float* __restrict__ bo)
{
    extern __shared__ char smem[];
    const uint32_t sb = smem_u32(smem);
    const int t = threadIdx.x;
    const int lane = t & 31, wid = t >> 5;
    const int wm = wid & 3;        // n group (4 x 32 rows)
    const int wn = wid >> 2;       // f group (2 x 32 cols)
    const int n0 = blockIdx.x * 128;
    const int f0 = blockIdx.y * 64;
    const int s  = blockIdx.z;

    // ---- async loads: A (x) 128x128 fp16, B (W) 3 x 64x128 fp16 ----
#pragma unroll
    for (int it = 0; it < 8; ++it) {
        int item = t + it * 256;               // 0..2047
        int row = item >> 4, seg = item & 15;
        cp16(sb + row * GROWB + seg * 16,
             g_xh + (size_t)(n0 + row) * (S_ * I_) + s * I_ + seg * 8);
    }
#pragma unroll
    for (int z = 0; z < 3; ++z) {
        const __half* wsrc = g_wgh + ((size_t)z * S_ + s) * F_ * I_;
#pragma unroll
        for (int it = 0; it < 4; ++it) {
            int item = t + it * 256;           // 0..1023: 64 rows x 16 segs
            int row = item >> 4, seg = item & 15;
            cp16(sb + GSB + z * GSBSZ + row * GROWB + seg * 16,
                 wsrc + (size_t)(f0 + row) * I_ + seg * 8);
        }
    }
    cp_commit();
    cp_wait<0>();
    __syncthreads();

    // ---- compute ----
    float C[3][8][4];
#pragma unroll
    for (int z = 0; z < 3; ++z)
#pragma unroll
        for (int i = 0; i < 8; ++i)
#pragma unroll
            for (int j = 0; j < 4; ++j) C[z][i][j] = 0.0f;

    const int a_row  = lane & 15;
    const int a_colb = (lane >> 4) * 16;
    const int b_row  = (lane & 7) + ((lane >> 4) & 1) * 8;
    const int b_colb = ((lane >> 3) & 1) * 16;

#pragma unroll
    for (int ks = 0; ks < 8; ++ks) {
        const int kb = ks * 32;
        uint32_t A[2][4];
#pragma unroll
        for (int mt = 0; mt < 2; ++mt)
            ldsm4(A[mt], sb + (wm * 32 + mt * 16 + a_row) * GROWB + a_colb + kb);
#pragma unroll
        for (int z = 0; z < 3; ++z) {
            uint32_t B[4][2];
#pragma unroll
            for (int p = 0; p < 2; ++p) {
                uint32_t r[4];
                ldsm4(r, sb + GSB + z * GSBSZ
                         + (wn * 32 + p * 16 + b_row) * GROWB + b_colb + kb);
                B[p * 2 + 0][0] = r[0]; B[p * 2 + 0][1] = r[1];
                B[p * 2 + 1][0] = r[2]; B[p * 2 + 1][1] = r[3];
            }
#pragma unroll
            for (int mt = 0; mt < 2; ++mt)
#pragma unroll
                for (int nt = 0; nt < 4; ++nt)
                    mma16816(C[z][mt * 4 + nt], A[mt], B[nt]);
        }
    }

    // ---- epilogue: bias + activations, h -> fp16 ----
#pragma unroll
    for (int mt = 0; mt < 2; ++mt) {
#pragma unroll
        for (int nt = 0; nt < 4; ++nt) {
            const int idx = mt * 4 + nt;
            const int r0 = n0 + wm * 32 + mt * 16 + (lane >> 2);
            const int f  = f0 + wn * 32 + nt * 8 + (lane & 3) * 2;
            float2 vbi = *(const float2*)&bi[s * F_ + f];
            float2 vbg = *(const float2*)&bg[s * F_ + f];
            float2 vbo = *(const float2*)&bo[s * F_ + f];
#pragma unroll
            for (int half = 0; half < 2; ++half) {
                const int r = r0 + half * 8;
                float pi0 = C[0][idx][half * 2 + 0] + vbi.x;
                float pi1 = C[0][idx][half * 2 + 1] + vbi.y;
                float pg0 = C[1][idx][half * 2 + 0] + vbg.x;
                float pg1 = C[1][idx][half * 2 + 1] + vbg.y;
                float po0 = C[2][idx][half * 2 + 0] + vbo.x;
                float po1 = C[2][idx][half * 2 + 1] + vbo.y;
                float h0 = sigmoid_f(po0) * tanh_f(sigmoid_f(pi0) * tanh_f(pg0));
                float h1 = sigmoid_f(po1) * tanh_f(sigmoid_f(pi1) * tanh_f(pg1));
                size_t ob = ((size_t)r * S_ + s) * F_ + f;
                *(uint32_t*)&g_h[ob] = pack2h(__float2half_rn(h0), __float2half_rn(h1));
            }
        }
    }
}

// ---------------------------------------------------------------------------
// Kernel B: out projection, single-pass fp16. CTA = 128(n) x 128(m),
// K=1024 in 16 chunks of 64, cp.async double-buffered.
// smem/stage: A [128][72h], B [128][72h]. 36864 B/stage x 2 = 73728.
// ---------------------------------------------------------------------------
#define OROWB 144
#define OMATSZ 18432
#define OSTAGE 36864
#define OUT_SMEM 73728

__global__ __launch_bounds__(256, 2) void out_mma(const float* __restrict__ bout,
                                                  float* __restrict__ out)
{
    extern __shared__ char smem[];
    const uint32_t sb = smem_u32(smem);
    const int t = threadIdx.x;
    const int lane = t & 31, wid = t >> 5;
    const int wn4 = wid & 3;       // n group (4 x 32 rows)
    const int wm2 = wid >> 2;      // m group (2 x 64 cols)
    const int n0 = blockIdx.x * 128;
    const int m0 = blockIdx.y * 128;
    const int s  = blockIdx.z;

    auto load_chunk = [&](int kc) {
        const uint32_t stg = sb + (kc & 1) * OSTAGE;
        const int k0 = kc * 64;
#pragma unroll
        for (int it = 0; it < 4; ++it) {
            int item = t + it * 256;           // 0..1023: 128 rows x 8 segs (K=64)
            int row = item >> 3, seg = item & 7;
            size_t asrc = ((size_t)(n0 + row) * S_ + s) * F_ + k0 + seg * 8;
            cp16(stg + 0 * OMATSZ + row * OROWB + seg * 16, g_h + asrc);
            size_t bsrc = ((size_t)s * M_ + m0 + row) * F_ + k0 + seg * 8;
            cp16(stg + 1 * OMATSZ + row * OROWB + seg * 16, g_wouth + bsrc);
        }
        cp_commit();
    };

    float C[16][4];
#pragma unroll
    for (int i = 0; i < 16; ++i)
#pragma unroll
        for (int j = 0; j < 4; ++j) C[i][j] = 0.0f;

    const int a_row  = lane & 15;
    const int a_colb = (lane >> 4) * 16;
    const int b_row  = (lane & 7) + ((lane >> 4) & 1) * 8;
    const int b_colb = ((lane >> 3) & 1) * 16;

    load_chunk(0);
    for (int kc = 0; kc < 16; ++kc) {
        if (kc < 15) load_chunk(kc + 1);
        if (kc < 15) cp_wait<1>(); else cp_wait<0>();
        __syncthreads();
        const uint32_t stg = sb + (kc & 1) * OSTAGE;
#pragma unroll
        for (int ks = 0; ks < 4; ++ks) {
            const int kb = ks * 32;
            uint32_t A[2][4];
#pragma unroll
            for (int mt = 0; mt < 2; ++mt)
                ldsm4(A[mt], stg + (wn4 * 32 + mt * 16 + a_row) * OROWB + a_colb + kb);
            uint32_t B[8][2];
#pragma unroll
            for (int p = 0; p < 4; ++p) {
                uint32_t rb = (wm2 * 64 + p * 16 + b_row) * OROWB + b_colb + kb;
                uint32_t r[4];
                ldsm4(r, stg + 1 * OMATSZ + rb);
                B[p * 2 + 0][0] = r[0]; B[p * 2 + 0][1] = r[1];
                B[p * 2 + 1][0] = r[2]; B[p * 2 + 1][1] = r[3];
            }
#pragma unroll
            for (int mt = 0; mt < 2; ++mt)
#pragma unroll
                for (int nt = 0; nt < 8; ++nt)
                    mma16816(C[mt * 8 + nt], A[mt], B[nt]);
        }
        __syncthreads();
    }

    // ---- epilogue: + bout, fp32 store ----
#pragma unroll
    for (int mt = 0; mt < 2; ++mt) {
#pragma unroll
        for (int nt = 0; nt < 8; ++nt) {
            const int idx = mt * 8 + nt;
            const int r0 = n0 + wn4 * 32 + mt * 16 + (lane >> 2);
            const int m  = m0 + wm2 * 64 + nt * 8 + (lane & 3) * 2;
            float2 vb = *(const float2*)&bout[s * M_ + m];
#pragma unroll
            for (int half = 0; half < 2; ++half) {
                const int r = r0 + half * 8;
                float2 ov;
                ov.x = C[idx][half * 2 + 0] + vb.x;
                ov.y = C[idx][half * 2 + 1] + vb.y;
                *(float2*)&out[(size_t)r * (S_ * M_) + s * M_ + m] = ov;
            }
        }
    }
}

// ---------------------------------------------------------------------------
// Launch. Inputs: modulation, Wxi, Whi, bi, Wxf, Whf, bf, Wxg, Whg, bg,
// Wxo, Who, bo, Wout, bout. Wh* unused (h0=0); Wxf/bf unused (c0=0).
// ---------------------------------------------------------------------------
extern "C" void kernel_launch(void* const* d_in, const int* in_sizes, int n_in,
                              void* d_out, int out_size)
{
    const float* mod  = (const float*)d_in[0];
    const float* Wxi  = (const float*)d_in[1];
    const float* bi   = (const float*)d_in[3];
    const float* Wxg  = (const float*)d_in[7];
    const float* bg   = (const float*)d_in[9];
    const float* Wxo  = (const float*)d_in[10];
    const float* bo   = (const float*)d_in[12];
    const float* Wout = (const float*)d_in[13];
    const float* bout = (const float*)d_in[14];
    float* out = (float*)d_out;

    cudaFuncSetAttribute(gates_mma, cudaFuncAttributeMaxDynamicSharedMemorySize, GATES_SMEM);
    cudaFuncSetAttribute(out_mma,   cudaFuncAttributeMaxDynamicSharedMemorySize, OUT_SMEM);

    convert_kernel<<<4096, 256>>>(mod, Wxi, Wxg, Wxo, Wout);
    gates_mma<<<dim3(8, 16, 8), 256, GATES_SMEM>>>(bi, bg, bo);
    out_mma<<<dim3(8, 4, 8), 256, OUT_SMEM>>>(bout, out);
}